// round 16
// baseline (speedup 1.0000x reference)
#include <cuda_runtime.h>
#include <cuda_fp16.h>
#include <cstdint>

#define N_ROWS 4096
#define DIM    512
#define BK 128
#define K_ITERS (N_ROWS / BK)            // 32
#define A_TILE (128 * 128)               // 16KB: 128 k-rows x 128B (64 m-cols)
#define B_TILE (64 * 128)                // 8KB: 128 k-rows packed 2/row (32 n-cols)
#define STAGE_BYTES (A_TILE + B_TILE)    // 24KB
#define STAGES 3
#define SMEM_GRAM (STAGES * STAGE_BYTES + 1024)   // 74752

#define NUNITS 672
#define NCTAS  444                       // 148 SMs x 3 co-resident

// Scratch: normalized fp16, SAME layout as input: [mat][n][d]
static __device__ __half g_normH[4][N_ROWS][DIM];
static __device__ float g_part[NUNITS];
static __device__ unsigned int g_work;   // work-steal counter (self-reset)
static __device__ unsigned int g_ctr;    // CTA completion counter (self-reset)

__constant__ int   c_symmat[4] = {3, 0, 1, 2};
__constant__ float c_symw[4]   = {3.f, 1.f, 1.f, 1.f};
// upper-triangle enumeration of 8x8 blocks of 64x64 (36 blocks)
__constant__ signed char c_bi36[36] = {0,0,0,0,0,0,0,0, 1,1,1,1,1,1,1, 2,2,2,2,2,2,
                                       3,3,3,3,3, 4,4,4,4, 5,5,5, 6,6, 7};
__constant__ signed char c_bj36[36] = {0,1,2,3,4,5,6,7, 1,2,3,4,5,6,7, 2,3,4,5,6,7,
                                       3,4,5,6,7, 4,5,6,7, 5,6,7, 6,7, 7};

// ---------------------------------------------------------------------------
__device__ __forceinline__ uint32_t s2u(const void* p) {
    uint32_t a;
    asm("{ .reg .u64 t; cvta.to.shared.u64 t, %1; cvt.u32.u64 %0, t; }"
        : "=r"(a) : "l"(p));
    return a;
}
__device__ __forceinline__ void cpasync16(uint32_t dst, const void* src) {
    asm volatile("cp.async.cg.shared.global [%0], [%1], 16;" :: "r"(dst), "l"(src) : "memory");
}
__device__ __forceinline__ void ldsm4t(uint32_t& r0, uint32_t& r1, uint32_t& r2,
                                       uint32_t& r3, uint32_t addr) {
    asm volatile("ldmatrix.sync.aligned.m8n8.x4.trans.shared.b16 {%0,%1,%2,%3}, [%4];"
                 : "=r"(r0), "=r"(r1), "=r"(r2), "=r"(r3) : "r"(addr));
}
// f16 x f16 -> f16 accumulate
__device__ __forceinline__ void mma16816_f16(uint32_t* c, const uint32_t* a,
                                             const uint32_t* b) {
    asm volatile(
        "mma.sync.aligned.m16n8k16.row.col.f16.f16.f16.f16 "
        "{%0,%1}, {%2,%3,%4,%5}, {%6,%7}, {%0,%1};"
        : "+r"(c[0]), "+r"(c[1])
        : "r"(a[0]), "r"(a[1]), "r"(a[2]), "r"(a[3]), "r"(b[0]), "r"(b[1]));
}

// ---------------------------------------------------------------------------
// K1: streaming per-row L2 normalize, fp32 [N,D] -> fp16 [N,D]. Warp per row.
// ---------------------------------------------------------------------------
__global__ __launch_bounds__(256) void norm_kernel(
    const float* __restrict__ in0, const float* __restrict__ in1,
    const float* __restrict__ in2, const float* __restrict__ in3)
{
    const int row  = blockIdx.x * 8 + (threadIdx.x >> 5);   // 0..16383
    const int lane = threadIdx.x & 31;
    const int mat  = row >> 12;
    const int r    = row & (N_ROWS - 1);
    const float* src = (mat == 0) ? in0 : (mat == 1) ? in1 : (mat == 2) ? in2 : in3;
    const float4* s4 = (const float4*)(src + (size_t)r * DIM);

    float4 v[4];
    float ss = 0.f;
#pragma unroll
    for (int j = 0; j < 4; j++) {
        v[j] = s4[lane + j * 32];
        ss += v[j].x * v[j].x + v[j].y * v[j].y + v[j].z * v[j].z + v[j].w * v[j].w;
    }
#pragma unroll
    for (int o = 16; o > 0; o >>= 1) ss += __shfl_xor_sync(0xffffffffu, ss, o);
    const float inv = rsqrtf(fmaxf(ss, 1e-24f));   // 1/max(||x||,1e-12)

    uint2* dst = (uint2*)&g_normH[mat][r][0];
#pragma unroll
    for (int j = 0; j < 4; j++) {
        __half2 h0 = __floats2half2_rn(v[j].x * inv, v[j].y * inv);
        __half2 h1 = __floats2half2_rn(v[j].z * inv, v[j].w * inv);
        uint2 pk = make_uint2(*(uint32_t*)&h0, *(uint32_t*)&h1);
        dst[lane + j * 32] = pk;
    }
}

// ---------------------------------------------------------------------------
// K2: persistent work-stealing over 672 units (64x32 x K=4096 each).
// 444 CTAs, 128 threads = 4 warps; warp w owns k-rows [32w,32w+32) of each
// BK=128 slab (per-warp cp.async groups + ldmatrix.trans -> no mainloop CTA
// barrier). f16 accumulate, fp32 promotion every 4 iters. Each unit writes its
// fixed g_part slot (deterministic final sum); last CTA of 444 reduces.
// ---------------------------------------------------------------------------
__global__ __launch_bounds__(128, 3) void gram_kernel(float* __restrict__ out)
{
    extern __shared__ char dyn[];
    __shared__ float red[4];
    __shared__ float fr[128];
    __shared__ int s_unit;
    __shared__ int s_last;

    const int tid  = threadIdx.x;
    const int lane = tid & 31;
    const int wid  = tid >> 5;
    const int w32  = wid * 32;
    const uint32_t dyn_sa = s2u(dyn);
    const uint32_t dynb = (dyn_sa + 1023) & ~1023u;
    char* dynp = dyn + (dynb - dyn_sa);

    // ---- ldmatrix.trans addressing (unit-independent)
    const int g8 = lane >> 3, i8 = lane & 7;
    uint32_t aRow[2], aXor[2], bRow[2], bXor[2], bHi4[2];
#pragma unroll
    for (int u = 0; u < 2; u++) {
        int ka = w32 + u * 16 + ((g8 >> 1) & 1) * 8 + i8;   // A: k+8 on g bit1
        aRow[u] = (uint32_t)ka * 128;
        aXor[u] = (uint32_t)(ka & 7);
        int kb = w32 + u * 16 + (g8 & 1) * 8 + i8;          // B: k+8 on g bit0
        bRow[u] = (uint32_t)(kb >> 1) * 128;
        bXor[u] = (uint32_t)((kb >> 1) & 7);
        bHi4[u] = (uint32_t)((kb & 1) << 2);
    }
    const uint32_t aC = (uint32_t)(g8 & 1);        // A: m+8 on g bit0
    const uint32_t bC = (uint32_t)((g8 >> 1) & 1); // B: n+8 on g bit1

    // ================= persistent loop =================
    for (;;) {
        if (tid == 0) s_unit = (int)atomicAdd(&g_work, 1u);
        __syncthreads();                 // broadcast + protects smem reuse
        const int bid = s_unit;
        if (bid >= NUNITS) break;

        // ---- decode unit
        int matL, matR, m0, n0; float w;
        if (bid < 288) {
            int p = bid / 72, r = bid % 72;
            int blk = r >> 1, half = r & 1;
            int bi = c_bi36[blk], bj = c_bj36[blk];
            matL = matR = c_symmat[p];
            m0 = bi * 64;
            n0 = bj * 64 + half * 32;
            w = c_symw[p] * ((bi == bj) ? 1.f : 2.f);
        } else {
            int q = bid - 288;
            matL = 3; matR = q >> 7;
            int r = q & 127;
            m0 = (r >> 4) * 64;
            n0 = (r & 15) * 32;
            w = -2.f;
        }
        const char* __restrict__ Ab = (const char*)&g_normH[matL][0][0] + m0 * 2;
        const char* __restrict__ Bb = (const char*)&g_normH[matR][0][0] + n0 * 2;

        // ---- per-warp loads: A 256 chunks (8/lane), B 128 chunks (4/lane)
        auto issue_loads = [&](int it) {
            const uint32_t sbase = dynb + (uint32_t)(it % STAGES) * STAGE_BYTES;
            const size_t gk = (size_t)(it * BK + w32) * (DIM * 2);
#pragma unroll
            for (int q = 0; q < 8; q++) {        // A
                int id = lane + q * 32;
                int rl = id >> 3, c = id & 7;
                int kr = w32 + rl;
                uint32_t sw = (uint32_t)kr * 128 + (uint32_t)((c ^ (kr & 7)) << 4);
                cpasync16(sbase + sw, Ab + gk + (size_t)rl * (DIM * 2) + c * 16);
            }
#pragma unroll
            for (int q = 0; q < 4; q++) {        // B (rows packed 2-per-128B)
                int id = lane + q * 32;
                int rl = id >> 2, c = id & 3;
                int kr = w32 + rl;
                int srow = kr >> 1;
                uint32_t cc = (uint32_t)(((kr & 1) << 2) | c);
                uint32_t sw = (uint32_t)srow * 128 + ((cc ^ (srow & 7)) << 4);
                cpasync16(sbase + A_TILE + sw, Bb + gk + (size_t)rl * (DIM * 2) + c * 16);
            }
            asm volatile("cp.async.commit_group;" ::: "memory");
        };

        float acc[4][4][4];
        uint32_t cf[4][4][2];
#pragma unroll
        for (int i = 0; i < 4; i++)
#pragma unroll
            for (int j = 0; j < 4; j++) {
#pragma unroll
                for (int r = 0; r < 4; r++) acc[i][j][r] = 0.f;
                cf[i][j][0] = 0u; cf[i][j][1] = 0u;
            }

        issue_loads(0);
        issue_loads(1);

        for (int it = 0; it < K_ITERS; ++it) {
            if (it < K_ITERS - 1)
                asm volatile("cp.async.wait_group 1;" ::: "memory");
            else
                asm volatile("cp.async.wait_group 0;" ::: "memory");
            __syncwarp();                        // per-warp pipeline

            const int nx = it + 2;
            if (nx < K_ITERS) issue_loads(nx);

            const uint32_t sA = dynb + (uint32_t)(it % STAGES) * STAGE_BYTES;
            const uint32_t sB = sA + A_TILE;

#pragma unroll
            for (int u = 0; u < 2; u++) {
                uint32_t a[4][4];
#pragma unroll
                for (int i = 0; i < 4; i++) {
                    uint32_t c = (uint32_t)(i * 2) + aC;
                    ldsm4t(a[i][0], a[i][1], a[i][2], a[i][3],
                           sA + aRow[u] + ((c ^ aXor[u]) << 4));
                }
                uint32_t bf[4][2];
#pragma unroll
                for (int j = 0; j < 2; j++) {
                    uint32_t cc = bHi4[u] | ((uint32_t)(j * 2) + bC);
                    uint32_t r0, r1, r2, r3;
                    ldsm4t(r0, r1, r2, r3, sB + bRow[u] + ((cc ^ bXor[u]) << 4));
                    bf[j * 2 + 0][0] = r0; bf[j * 2 + 0][1] = r1;
                    bf[j * 2 + 1][0] = r2; bf[j * 2 + 1][1] = r3;
                }
#pragma unroll
                for (int i = 0; i < 4; i++)
#pragma unroll
                    for (int j = 0; j < 4; j++)
                        mma16816_f16(cf[i][j], a[i], bf[j]);
            }

            if ((it & 3) == 3) {                 // promote f16 -> fp32 every 512 k
#pragma unroll
                for (int i = 0; i < 4; i++)
#pragma unroll
                    for (int j = 0; j < 4; j++) {
                        float2 f0 = __half22float2(*(__half2*)&cf[i][j][0]);
                        float2 f1 = __half22float2(*(__half2*)&cf[i][j][1]);
                        acc[i][j][0] += f0.x; acc[i][j][1] += f0.y;
                        acc[i][j][2] += f1.x; acc[i][j][3] += f1.y;
                        cf[i][j][0] = 0u; cf[i][j][1] = 0u;
                    }
            }
        }

        // ---- merge 4 warp k-partials via smem (stages are drained)
        float* exch = (float*)dynp;
        __syncthreads();
#pragma unroll
        for (int i = 0; i < 4; i++)
#pragma unroll
            for (int j = 0; j < 4; j++)
#pragma unroll
                for (int r = 0; r < 4; r++)
                    exch[wid * 2048 + (i * 16 + j * 4 + r) * 32 + lane] = acc[i][j][r];
        __syncthreads();

        float ss = 0.f;
#pragma unroll
        for (int s = 0; s < 16; s++) {
            int f = tid + s * 128;
            float x = exch[f] + exch[2048 + f] + exch[4096 + f] + exch[6144 + f];
            ss += x * x;
        }
#pragma unroll
        for (int o = 16; o > 0; o >>= 1) ss += __shfl_xor_sync(0xffffffffu, ss, o);
        if (lane == 0) red[wid] = ss;
        __syncthreads();
        if (tid == 0)
            g_part[bid] = w * (red[0] + red[1] + red[2] + red[3]);
        // loop-top __syncthreads orders exch reuse before next unit's loads
    }

    // ================= completion + deterministic reduction =================
    if (tid == 0) {
        __threadfence();
        unsigned int old = atomicAdd(&g_ctr, 1u);
        s_last = (old == NCTAS - 1) ? 1 : 0;
    }
    __syncthreads();

    if (s_last) {
        float v = 0.f;
#pragma unroll
        for (int k = 0; k < 6; k++) {            // 672 = 5*128 + 32
            int idx = tid + k * 128;
            if (idx < NUNITS) v += __ldcg(&g_part[idx]);
        }
        fr[tid] = v;
        __syncthreads();
#pragma unroll
        for (int o = 64; o > 0; o >>= 1) {
            if (tid < o) fr[tid] += fr[tid + o];
            __syncthreads();
        }
        if (tid == 0) {
            out[0] = fr[0] * (100.0f / 16777216.0f);   // (1/T^2)/N^2
            g_ctr = 0;                                 // self-reset for graph replay
            g_work = 0;
        }
    }
}

// ---------------------------------------------------------------------------
extern "C" void kernel_launch(void* const* d_in, const int* in_sizes, int n_in,
                              void* d_out, int out_size)
{
    const float* rgb   = (const float*)d_in[0];
    const float* depth = (const float*)d_in[1];
    const float* ir    = (const float*)d_in[2];
    const float* tmat  = (const float*)d_in[3];
    float* out = (float*)d_out;

    cudaFuncSetAttribute(gram_kernel,
                         cudaFuncAttributeMaxDynamicSharedMemorySize, SMEM_GRAM);

    norm_kernel<<<2048, 256>>>(rgb, depth, ir, tmat);
    gram_kernel<<<NCTAS, 128, SMEM_GRAM>>>(out);
}

// round 17
// speedup vs baseline: 1.4077x; 1.4077x over previous
#include <cuda_runtime.h>
#include <cuda_fp16.h>
#include <cstdint>

#define N_ROWS 4096
#define DIM    512
#define BK 128
#define K_ITERS (N_ROWS / BK)            // 32
#define A_TILE (64 * 128)                // 8KB: 128 k-rows packed 2/row (32 m-cols)
#define B_TILE (64 * 128)                // 8KB: same for 32 n-cols
#define STAGE_BYTES (A_TILE + B_TILE)    // 16KB
#define STAGES 3
#define SMEM_GRAM (STAGES * STAGE_BYTES + 1024)   // 50176

#define NUNITS 1312                      // 544 symmetric + 768 cross, 32x32 units

// Scratch: normalized fp16, SAME layout as input: [mat][n][d]
static __device__ __half g_normH[4][N_ROWS][DIM];
static __device__ float g_part[NUNITS];
static __device__ unsigned int g_ctr;    // zero-init; self-reset by last block

__constant__ int   c_symmat[4] = {3, 0, 1, 2};
__constant__ float c_symw[4]   = {3.f, 1.f, 1.f, 1.f};
// upper-triangle enumeration of 16x16 blocks of 32x32 (136 blocks)
__constant__ signed char c_bi136[136] = {
    0,0,0,0,0,0,0,0,0,0,0,0,0,0,0,0,
    1,1,1,1,1,1,1,1,1,1,1,1,1,1,1,
    2,2,2,2,2,2,2,2,2,2,2,2,2,2,
    3,3,3,3,3,3,3,3,3,3,3,3,3,
    4,4,4,4,4,4,4,4,4,4,4,4,
    5,5,5,5,5,5,5,5,5,5,5,
    6,6,6,6,6,6,6,6,6,6,
    7,7,7,7,7,7,7,7,7,
    8,8,8,8,8,8,8,8,
    9,9,9,9,9,9,9,
    10,10,10,10,10,10,
    11,11,11,11,11,
    12,12,12,12,
    13,13,13,
    14,14,
    15};
__constant__ signed char c_bj136[136] = {
    0,1,2,3,4,5,6,7,8,9,10,11,12,13,14,15,
    1,2,3,4,5,6,7,8,9,10,11,12,13,14,15,
    2,3,4,5,6,7,8,9,10,11,12,13,14,15,
    3,4,5,6,7,8,9,10,11,12,13,14,15,
    4,5,6,7,8,9,10,11,12,13,14,15,
    5,6,7,8,9,10,11,12,13,14,15,
    6,7,8,9,10,11,12,13,14,15,
    7,8,9,10,11,12,13,14,15,
    8,9,10,11,12,13,14,15,
    9,10,11,12,13,14,15,
    10,11,12,13,14,15,
    11,12,13,14,15,
    12,13,14,15,
    13,14,15,
    14,15,
    15};

// ---------------------------------------------------------------------------
__device__ __forceinline__ uint32_t s2u(const void* p) {
    uint32_t a;
    asm("{ .reg .u64 t; cvta.to.shared.u64 t, %1; cvt.u32.u64 %0, t; }"
        : "=r"(a) : "l"(p));
    return a;
}
__device__ __forceinline__ void cpasync16(uint32_t dst, const void* src) {
    asm volatile("cp.async.cg.shared.global [%0], [%1], 16;" :: "r"(dst), "l"(src) : "memory");
}
__device__ __forceinline__ void ldsm4t(uint32_t& r0, uint32_t& r1, uint32_t& r2,
                                       uint32_t& r3, uint32_t addr) {
    asm volatile("ldmatrix.sync.aligned.m8n8.x4.trans.shared.b16 {%0,%1,%2,%3}, [%4];"
                 : "=r"(r0), "=r"(r1), "=r"(r2), "=r"(r3) : "r"(addr));
}
// f16 x f16 -> f16 accumulate
__device__ __forceinline__ void mma16816_f16(uint32_t* c, const uint32_t* a,
                                             const uint32_t* b) {
    asm volatile(
        "mma.sync.aligned.m16n8k16.row.col.f16.f16.f16.f16 "
        "{%0,%1}, {%2,%3,%4,%5}, {%6,%7}, {%0,%1};"
        : "+r"(c[0]), "+r"(c[1])
        : "r"(a[0]), "r"(a[1]), "r"(a[2]), "r"(a[3]), "r"(b[0]), "r"(b[1]));
}

// ---------------------------------------------------------------------------
// K1: streaming per-row L2 normalize, fp32 [N,D] -> fp16 [N,D]. Warp per row.
// ---------------------------------------------------------------------------
__global__ __launch_bounds__(256) void norm_kernel(
    const float* __restrict__ in0, const float* __restrict__ in1,
    const float* __restrict__ in2, const float* __restrict__ in3)
{
    const int row  = blockIdx.x * 8 + (threadIdx.x >> 5);   // 0..16383
    const int lane = threadIdx.x & 31;
    const int mat  = row >> 12;
    const int r    = row & (N_ROWS - 1);
    const float* src = (mat == 0) ? in0 : (mat == 1) ? in1 : (mat == 2) ? in2 : in3;
    const float4* s4 = (const float4*)(src + (size_t)r * DIM);

    float4 v[4];
    float ss = 0.f;
#pragma unroll
    for (int j = 0; j < 4; j++) {
        v[j] = s4[lane + j * 32];
        ss += v[j].x * v[j].x + v[j].y * v[j].y + v[j].z * v[j].z + v[j].w * v[j].w;
    }
#pragma unroll
    for (int o = 16; o > 0; o >>= 1) ss += __shfl_xor_sync(0xffffffffu, ss, o);
    const float inv = rsqrtf(fmaxf(ss, 1e-24f));   // 1/max(||x||,1e-12)

    uint2* dst = (uint2*)&g_normH[mat][r][0];
#pragma unroll
    for (int j = 0; j < 4; j++) {
        __half2 h0 = __floats2half2_rn(v[j].x * inv, v[j].y * inv);
        __half2 h1 = __floats2half2_rn(v[j].z * inv, v[j].w * inv);
        uint2 pk = make_uint2(*(uint32_t*)&h0, *(uint32_t*)&h1);
        dst[lane + j * 32] = pk;
    }
}

// ---------------------------------------------------------------------------
// K2: 1312 units, each 32x32 x full K=4096 (static grid, ~2.96 waves over
// 444 slots). 128 threads = 4 warps; warp w owns k-rows [32w,32w+32) of each
// BK=128 slab: per-warp cp.async groups + ldmatrix.trans -> no CTA barrier in
// the mainloop. f16 accumulate, fp32 promotion every 4 iters. k-partials
// merged via smem; fused weighted ||C||_F^2 + last-block reduction.
// smem tiles: rows packed 2-per-128B (A and B identically).
// ---------------------------------------------------------------------------
__global__ __launch_bounds__(128, 3) void gram_kernel(float* __restrict__ out)
{
    extern __shared__ char dyn[];
    __shared__ float red[4];
    __shared__ float fr[128];
    __shared__ int s_last;

    // ---- decode unit
    const int bid = blockIdx.x;
    int matL, matR, m0, n0; float w;
    if (bid < 544) {
        int p = bid >> 7;                // bid/136 via: 544 = 4*136
        int t = bid - p * 136;
        // p computed as bid/136 exactly:
        p = bid / 136; t = bid % 136;
        int bi = c_bi136[t], bj = c_bj136[t];
        matL = matR = c_symmat[p];
        m0 = bi * 32;
        n0 = bj * 32;
        w = c_symw[p] * ((bi == bj) ? 1.f : 2.f);
    } else {
        int q = bid - 544;
        matL = 3; matR = q >> 8;
        int r = q & 255;
        m0 = (r >> 4) * 32;
        n0 = (r & 15) * 32;
        w = -2.f;
    }
    const char* __restrict__ Ab = (const char*)&g_normH[matL][0][0] + m0 * 2;
    const char* __restrict__ Bb = (const char*)&g_normH[matR][0][0] + n0 * 2;

    const int tid  = threadIdx.x;
    const int lane = tid & 31;
    const int wid  = tid >> 5;
    const int w32  = wid * 32;                   // this warp's k-row base in slab
    const uint32_t dyn_sa = s2u(dyn);
    const uint32_t dynb = (dyn_sa + 1023) & ~1023u;
    char* dynp = dyn + (dynb - dyn_sa);

    // ---- per-warp loads: A 128 chunks (4/lane), B 128 chunks (4/lane)
    auto issue_loads = [&](int it) {
        const uint32_t sbase = dynb + (uint32_t)(it % STAGES) * STAGE_BYTES;
        const size_t gk = (size_t)(it * BK + w32) * (DIM * 2);   // k-row byte base
#pragma unroll
        for (int q = 0; q < 4; q++) {            // A (rows packed 2-per-128B)
            int id = lane + q * 32;              // 0..127
            int rl = id >> 2, c = id & 3;        // local k-row, 16B chunk
            int kr = w32 + rl;
            int srow = kr >> 1;
            uint32_t cc = (uint32_t)(((kr & 1) << 2) | c);
            uint32_t sw = (uint32_t)srow * 128 + ((cc ^ (srow & 7)) << 4);
            cpasync16(sbase + sw, Ab + gk + (size_t)rl * (DIM * 2) + c * 16);
        }
#pragma unroll
        for (int q = 0; q < 4; q++) {            // B (rows packed 2-per-128B)
            int id = lane + q * 32;              // 0..127
            int rl = id >> 2, c = id & 3;
            int kr = w32 + rl;
            int srow = kr >> 1;
            uint32_t cc = (uint32_t)(((kr & 1) << 2) | c);
            uint32_t sw = (uint32_t)srow * 128 + ((cc ^ (srow & 7)) << 4);
            cpasync16(sbase + A_TILE + sw, Bb + gk + (size_t)rl * (DIM * 2) + c * 16);
        }
        asm volatile("cp.async.commit_group;" ::: "memory");
    };

    // ---- ldmatrix.trans addressing (per u = k16-half of this warp's 32 rows)
    const int g8 = lane >> 3, i8 = lane & 7;
    uint32_t aRow[2], aXor[2], aHi4[2], bRow[2], bXor[2], bHi4[2];
#pragma unroll
    for (int u = 0; u < 2; u++) {
        int ka = w32 + u * 16 + ((g8 >> 1) & 1) * 8 + i8;   // A: k+8 on g bit1
        aRow[u] = (uint32_t)(ka >> 1) * 128;
        aXor[u] = (uint32_t)((ka >> 1) & 7);
        aHi4[u] = (uint32_t)((ka & 1) << 2);
        int kb = w32 + u * 16 + (g8 & 1) * 8 + i8;          // B: k+8 on g bit0
        bRow[u] = (uint32_t)(kb >> 1) * 128;
        bXor[u] = (uint32_t)((kb >> 1) & 7);
        bHi4[u] = (uint32_t)((kb & 1) << 2);
    }
    const uint32_t aC = (uint32_t)(g8 & 1);        // A: m+8 on g bit0
    const uint32_t bC = (uint32_t)((g8 >> 1) & 1); // B: n+8 on g bit1

    float acc[2][4][4];
    uint32_t cf[2][4][2];
#pragma unroll
    for (int i = 0; i < 2; i++)
#pragma unroll
        for (int j = 0; j < 4; j++) {
#pragma unroll
            for (int r = 0; r < 4; r++) acc[i][j][r] = 0.f;
            cf[i][j][0] = 0u; cf[i][j][1] = 0u;
        }

    issue_loads(0);
    issue_loads(1);

    for (int it = 0; it < K_ITERS; ++it) {
        if (it < K_ITERS - 1)
            asm volatile("cp.async.wait_group 1;" ::: "memory");
        else
            asm volatile("cp.async.wait_group 0;" ::: "memory");
        __syncwarp();                            // per-warp pipeline: no CTA barrier

        const int nx = it + 2;
        if (nx < K_ITERS) issue_loads(nx);

        const uint32_t sA = dynb + (uint32_t)(it % STAGES) * STAGE_BYTES;
        const uint32_t sB = sA + A_TILE;

#pragma unroll
        for (int u = 0; u < 2; u++) {
            uint32_t a[2][4];
#pragma unroll
            for (int i = 0; i < 2; i++) {
                uint32_t cc = aHi4[u] | ((uint32_t)(i * 2) + aC);
                ldsm4t(a[i][0], a[i][1], a[i][2], a[i][3],
                       sA + aRow[u] + ((cc ^ aXor[u]) << 4));
            }
            uint32_t bf[4][2];
#pragma unroll
            for (int j = 0; j < 2; j++) {
                uint32_t cc = bHi4[u] | ((uint32_t)(j * 2) + bC);
                uint32_t r0, r1, r2, r3;
                ldsm4t(r0, r1, r2, r3, sB + bRow[u] + ((cc ^ bXor[u]) << 4));
                bf[j * 2 + 0][0] = r0; bf[j * 2 + 0][1] = r1;
                bf[j * 2 + 1][0] = r2; bf[j * 2 + 1][1] = r3;
            }
#pragma unroll
            for (int i = 0; i < 2; i++)
#pragma unroll
                for (int j = 0; j < 4; j++)
                    mma16816_f16(cf[i][j], a[i], bf[j]);
        }

        if ((it & 3) == 3) {                     // promote f16 -> fp32 every 512 k
#pragma unroll
            for (int i = 0; i < 2; i++)
#pragma unroll
                for (int j = 0; j < 4; j++) {
                    float2 f0 = __half22float2(*(__half2*)&cf[i][j][0]);
                    float2 f1 = __half22float2(*(__half2*)&cf[i][j][1]);
                    acc[i][j][0] += f0.x; acc[i][j][1] += f0.y;
                    acc[i][j][2] += f1.x; acc[i][j][3] += f1.y;
                    cf[i][j][0] = 0u; cf[i][j][1] = 0u;
                }
        }
    }

    // ---- merge 4 warp k-partials via smem (identical register layouts)
    float* exch = (float*)dynp;
    __syncthreads();                             // all warps done with their stages
#pragma unroll
    for (int i = 0; i < 2; i++)
#pragma unroll
        for (int j = 0; j < 4; j++)
#pragma unroll
            for (int r = 0; r < 4; r++)
                exch[wid * 1024 + (i * 16 + j * 4 + r) * 32 + lane] = acc[i][j][r];
    __syncthreads();

    float ss = 0.f;
#pragma unroll
    for (int s = 0; s < 8; s++) {
        int f = tid + s * 128;
        float x = exch[f] + exch[1024 + f] + exch[2048 + f] + exch[3072 + f];
        ss += x * x;
    }
#pragma unroll
    for (int o = 16; o > 0; o >>= 1) ss += __shfl_xor_sync(0xffffffffu, ss, o);
    if (lane == 0) red[wid] = ss;
    __syncthreads();
    if (tid == 0) {
        g_part[bid] = w * (red[0] + red[1] + red[2] + red[3]);
        __threadfence();
        unsigned int old = atomicAdd(&g_ctr, 1u);
        s_last = (old == NUNITS - 1) ? 1 : 0;
    }
    __syncthreads();

    // last finished block: deterministic fixed-order final reduction
    if (s_last) {
        float v = 0.f;
#pragma unroll
        for (int k = 0; k < 11; k++) {           // 1312 = 10*128 + 32
            int idx = tid + k * 128;
            if (idx < NUNITS) v += __ldcg(&g_part[idx]);
        }
        fr[tid] = v;
        __syncthreads();
#pragma unroll
        for (int o = 64; o > 0; o >>= 1) {
            if (tid < o) fr[tid] += fr[tid + o];
            __syncthreads();
        }
        if (tid == 0) {
            out[0] = fr[0] * (100.0f / 16777216.0f);   // (1/T^2)/N^2
            g_ctr = 0;                                 // self-reset for graph replay
        }
    }
}

// ---------------------------------------------------------------------------
extern "C" void kernel_launch(void* const* d_in, const int* in_sizes, int n_in,
                              void* d_out, int out_size)
{
    const float* rgb   = (const float*)d_in[0];
    const float* depth = (const float*)d_in[1];
    const float* ir    = (const float*)d_in[2];
    const float* tmat  = (const float*)d_in[3];
    float* out = (float*)d_out;

    cudaFuncSetAttribute(gram_kernel,
                         cudaFuncAttributeMaxDynamicSharedMemorySize, SMEM_GRAM);

    norm_kernel<<<2048, 256>>>(rgb, depth, ir, tmat);
    gram_kernel<<<NUNITS, 128, SMEM_GRAM>>>(out);
}